// round 1
// baseline (speedup 1.0000x reference)
#include <cuda_runtime.h>
#include <cstdint>

#define N_USERS 100000
#define M_ITEMS 200000
#define N_NODES 300000
#define N_EDGES 1200000
#define BATCH   4096

// ---------------- scratch (device globals: allocation-free rule) -------------
__device__ float4 g_ego4 [N_NODES * 16];
__device__ float4 g_side4[N_NODES * 16];
__device__ float4 g_acc4 [N_NODES * 16];

// ---------------- f32x2 helpers ----------------------------------------------
__device__ __forceinline__ uint64_t lds64(uint32_t a) {
    uint64_t v; asm volatile("ld.shared.b64 %0, [%1];" : "=l"(v) : "r"(a)); return v;
}
__device__ __forceinline__ void lds128(uint64_t& x, uint64_t& y, uint32_t a) {
    asm volatile("ld.shared.v2.u64 {%0,%1}, [%2];" : "=l"(x), "=l"(y) : "r"(a));
}
__device__ __forceinline__ uint64_t fma2(uint64_t a, uint64_t b, uint64_t c) {
    uint64_t d; asm("fma.rn.f32x2 %0, %1, %2, %3;" : "=l"(d) : "l"(a), "l"(b), "l"(c)); return d;
}
__device__ __forceinline__ uint64_t packf2(float lo, float hi) {
    uint64_t p; asm("mov.b64 %0, {%1,%2};" : "=l"(p) : "f"(lo), "f"(hi)); return p;
}
__device__ __forceinline__ void unpackf2(float& lo, float& hi, uint64_t p) {
    asm("mov.b64 {%0,%1}, %2;" : "=f"(lo), "=f"(hi) : "l"(p));
}
__device__ __forceinline__ uint32_t s2u(const void* p) {
    return (uint32_t)__cvta_generic_to_shared(p);
}

// ---------------- init: ego = concat(user,item); acc = ego -------------------
__global__ __launch_bounds__(256) void init_kernel(const float4* __restrict__ ue,
                                                   const float4* __restrict__ ie) {
    int i = blockIdx.x * 256 + threadIdx.x;
    if (i >= N_NODES * 16) return;
    float4 v = (i < N_USERS * 16) ? ue[i] : ie[i - N_USERS * 16];
    g_ego4[i] = v;
    g_acc4[i] = v;
}

__global__ __launch_bounds__(256) void zero_side_kernel() {
    int i = blockIdx.x * 256 + threadIdx.x;
    if (i < N_NODES * 16) g_side4[i] = make_float4(0.f, 0.f, 0.f, 0.f);
}

// ---------------- spmm: side[r] += vals[e] * ego[cols[e]] --------------------
// 16 threads per edge, float4 per thread, 128-bit vector RED to L2.
__global__ __launch_bounds__(256) void spmm_kernel(const int*   __restrict__ rows,
                                                   const int*   __restrict__ cols,
                                                   const float* __restrict__ vals) {
    int gid = blockIdx.x * 256 + threadIdx.x;
    int e = gid >> 4;
    if (e >= N_EDGES) return;
    int q = gid & 15;
    int r = __ldg(rows + e);
    int c = __ldg(cols + e);
    float v = __ldg(vals + e);
    float4 x = g_ego4[c * 16 + q];
    float* p = (float*)g_side4 + ((size_t)r * 64 + q * 4);
    asm volatile("red.global.add.v4.f32 [%0], {%1,%2,%3,%4};"
                 :: "l"(p), "f"(v * x.x), "f"(v * x.y), "f"(v * x.z), "f"(v * x.w)
                 : "memory");
}

// ---------------- transform: y = LReLU(s@Wgc + (e*s)@Wbi + b); norm; acc -----
#define TTILE     128
#define SS_STRIDE 65                       // float2 per row (pad kills conflicts)
#define SS_BYTES  (TTILE * SS_STRIDE * 8)  // 66560
#define SMEM_TR   (2 * SS_BYTES + 2 * 64 * 64 * 4)  // 165888

__global__ __launch_bounds__(256, 1) void transform_kernel(const float* __restrict__ Wgc,
                                                           const float* __restrict__ bgc,
                                                           const float* __restrict__ Wbi,
                                                           const float* __restrict__ bbi) {
    extern __shared__ unsigned char smem[];
    float2* sS  = (float2*)smem;                       // dup side  [128][65]
    float2* sU  = (float2*)(smem + SS_BYTES);          // dup ego*side
    float*  sWg = (float*)(smem + 2 * SS_BYTES);       // [64][64]
    float*  sWb = sWg + 64 * 64;

    const float* side = (const float*)g_side4;
    const float* ego  = (const float*)g_ego4;

    int tid  = threadIdx.x;
    int base = blockIdx.x * TTILE;

    // --- load tiles (scalar coalesced loads, conflict-free dup stores) ---
    #pragma unroll
    for (int it = 0; it < 8; ++it) {
        int idx = it * 256 + tid;            // 0..2047
        int lr  = idx >> 4;                  // 0..127
        int q   = idx & 15;
        int n   = base + lr;
        float sv[4] = {0.f, 0.f, 0.f, 0.f};
        float ev[4] = {0.f, 0.f, 0.f, 0.f};
        if (n < N_NODES) {
            size_t o = (size_t)n * 64 + q;
            #pragma unroll
            for (int c = 0; c < 4; ++c) { sv[c] = side[o + 16 * c]; ev[c] = ego[o + 16 * c]; }
        }
        float2* ps = sS + lr * SS_STRIDE;
        float2* pu = sU + lr * SS_STRIDE;
        #pragma unroll
        for (int c = 0; c < 4; ++c) {
            ps[q + 16 * c] = make_float2(sv[c], sv[c]);
            float u = ev[c] * sv[c];
            pu[q + 16 * c] = make_float2(u, u);
        }
    }
    for (int i = tid; i < 4096; i += 256) { sWg[i] = Wgc[i]; sWb[i] = Wbi[i]; }
    __syncthreads();

    // --- register-tiled GEMM: thread = 4 rows x 8 cols, f32x2 packed over cols
    int cq = tid & 7;     // col group: cols 8*cq .. 8*cq+7
    int rq = tid >> 3;    // row group: rows 4*rq .. 4*rq+3

    uint32_t aS  = s2u(sS + (4 * rq) * SS_STRIDE);
    uint32_t aU  = s2u(sU + (4 * rq) * SS_STRIDE);
    uint32_t aWg = s2u(sWg + 8 * cq);
    uint32_t aWb = s2u(sWb + 8 * cq);

    uint64_t acc[4][4];
    #pragma unroll
    for (int cp = 0; cp < 4; ++cp) {
        int c0 = 8 * cq + 2 * cp;
        uint64_t p = packf2(bgc[c0] + bbi[c0], bgc[c0 + 1] + bbi[c0 + 1]);
        acc[0][cp] = p; acc[1][cp] = p; acc[2][cp] = p; acc[3][cp] = p;
    }

    #pragma unroll 8
    for (int j = 0; j < 64; ++j) {
        uint64_t sv[4], uv[4], wg[4], wb[4];
        #pragma unroll
        for (int r = 0; r < 4; ++r) {
            sv[r] = lds64(aS + j * 8 + r * (SS_STRIDE * 8));
            uv[r] = lds64(aU + j * 8 + r * (SS_STRIDE * 8));
        }
        lds128(wg[0], wg[1], aWg + j * 256);
        lds128(wg[2], wg[3], aWg + j * 256 + 16);
        lds128(wb[0], wb[1], aWb + j * 256);
        lds128(wb[2], wb[3], aWb + j * 256 + 16);
        #pragma unroll
        for (int r = 0; r < 4; ++r)
            #pragma unroll
            for (int cp = 0; cp < 4; ++cp)
                acc[r][cp] = fma2(uv[r], wb[cp], fma2(sv[r], wg[cp], acc[r][cp]));
    }

    // --- leaky relu into shared, then row-norm + store ---
    __syncthreads();
    float* sY = (float*)smem;  // [128][64], reuses sS region
    #pragma unroll
    for (int r = 0; r < 4; ++r) {
        #pragma unroll
        for (int cp = 0; cp < 4; ++cp) {
            float lo, hi;
            unpackf2(lo, hi, acc[r][cp]);
            lo = lo > 0.f ? lo : 0.2f * lo;
            hi = hi > 0.f ? hi : 0.2f * hi;
            int row = 4 * rq + r, col = 8 * cq + 2 * cp;
            sY[row * 64 + col]     = lo;
            sY[row * 64 + col + 1] = hi;
        }
    }
    __syncthreads();

    int lane = tid & 31, warp = tid >> 5;
    float* ego_w = (float*)g_ego4;
    float* acc_w = (float*)g_acc4;
    for (int r = warp; r < TTILE; r += 8) {
        float v1 = sY[r * 64 + lane];
        float v2 = sY[r * 64 + 32 + lane];
        float ss = v1 * v1 + v2 * v2;
        #pragma unroll
        for (int o = 16; o > 0; o >>= 1) ss += __shfl_xor_sync(0xffffffffu, ss, o);
        float sc = 1.0f / fmaxf(sqrtf(ss), 1e-12f);
        v1 *= sc; v2 *= sc;
        int n = base + r;
        if (n < N_NODES) {
            size_t o = (size_t)n * 64 + lane;
            ego_w[o]      = v1;
            ego_w[o + 32] = v2;
            acc_w[o]      += v1;
            acc_w[o + 32] += v2;
        }
    }
}

// ---------------- output: dot(mean_u, mean_i) = dot(acc_u, acc_i)/16 ---------
__global__ __launch_bounds__(256) void out_kernel(const int* __restrict__ users,
                                                  const int* __restrict__ items,
                                                  float* __restrict__ out) {
    int b = blockIdx.x * 8 + (threadIdx.x >> 5);
    int lane = threadIdx.x & 31;
    if (b >= BATCH) return;
    int u = __ldg(users + b);
    int i = __ldg(items + b);
    const float* pu = (const float*)g_acc4 + (size_t)u * 64;
    const float* pi = (const float*)g_acc4 + (size_t)(N_USERS + i) * 64;
    float s = pu[lane] * pi[lane] + pu[lane + 32] * pi[lane + 32];
    #pragma unroll
    for (int o = 16; o > 0; o >>= 1) s += __shfl_xor_sync(0xffffffffu, s, o);
    if (lane == 0) out[b] = s * (1.0f / 16.0f);
}

// ---------------- host launcher ----------------------------------------------
extern "C" void kernel_launch(void* const* d_in, const int* in_sizes, int n_in,
                              void* d_out, int out_size) {
    const int*   users    = (const int*)  d_in[0];
    const int*   items    = (const int*)  d_in[1];
    const int*   rows     = (const int*)  d_in[2];
    const int*   cols     = (const int*)  d_in[3];
    const float* vals     = (const float*)d_in[4];
    const float* user_emb = (const float*)d_in[5];
    const float* item_emb = (const float*)d_in[6];
    const float* W_gc     = (const float*)d_in[7];
    const float* b_gc     = (const float*)d_in[8];
    const float* W_bi     = (const float*)d_in[9];
    const float* b_bi     = (const float*)d_in[10];
    float*       out      = (float*)d_out;

    cudaFuncSetAttribute(transform_kernel,
                         cudaFuncAttributeMaxDynamicSharedMemorySize, SMEM_TR);

    const int nvec = N_NODES * 16;
    init_kernel<<<(nvec + 255) / 256, 256>>>((const float4*)user_emb,
                                             (const float4*)item_emb);

    for (int k = 0; k < 3; ++k) {
        zero_side_kernel<<<(nvec + 255) / 256, 256>>>();
        spmm_kernel<<<(N_EDGES * 16) / 256, 256>>>(rows, cols, vals);
        transform_kernel<<<(N_NODES + TTILE - 1) / TTILE, 256, SMEM_TR>>>(
            W_gc + k * 64 * 64, b_gc + k * 64,
            W_bi + k * 64 * 64, b_bi + k * 64);
    }

    out_kernel<<<BATCH / 8, 256>>>(users, items, out);
}